// round 8
// baseline (speedup 1.0000x reference)
#include <cuda_runtime.h>
#include <cuda_bf16.h>

// logits[i] = sum_{(i,j) in E} Wt[j] + b ; out = log_softmax(logits, axis=1)
// N=100000, E=3200000, C=64. edge_index int32 [2,E].
//
// R6: R4's pull kernel (broadcast scol loads — R5's shfl-broadcast version
// serialized on shfl->load chains, +160us) + fused scan + 4-edge-per-thread
// build_scol for atomic MLP.

#define C 64
#define MAX_N 100000
#define MAX_E 3200000
#define SCAN_THREADS 1024

__device__ int g_counts[MAX_N + 1];
__device__ int g_rowptr[MAX_N + 1];
__device__ int g_cursor[MAX_N + 1];
__device__ int g_scol[MAX_E];

// ---------------- CSR build ----------------

__global__ void zero_counts_kernel(int N) {
    int i = blockIdx.x * blockDim.x + threadIdx.x;
    if (i <= N) g_counts[i] = 0;
}

__global__ void hist_kernel(const int* __restrict__ ei, int E) {
    int i = blockIdx.x * blockDim.x + threadIdx.x;
    int e4 = i * 4;
    if (e4 + 4 <= E) {
        int4 r = __ldg(reinterpret_cast<const int4*>(ei + e4));
        atomicAdd(&g_counts[r.x], 1);
        atomicAdd(&g_counts[r.y], 1);
        atomicAdd(&g_counts[r.z], 1);
        atomicAdd(&g_counts[r.w], 1);
    } else {
        for (int e = e4; e < E; e++) atomicAdd(&g_counts[ei[e]], 1);
    }
}

// Single-block fused exclusive scan: g_counts[0..N) -> g_rowptr/g_cursor, rowptr[N]=E
__global__ void fused_scan_kernel(int N, int E) {
    __shared__ int warp_tot[32];
    int t = threadIdx.x;           // 0..1023
    int lane = t & 31, w = t >> 5;

    int chunk = (N + SCAN_THREADS - 1) / SCAN_THREADS;
    int lo = t * chunk;
    int hi = min(lo + chunk, N);

    int tsum = 0;
    for (int i = lo; i < hi; i++) tsum += g_counts[i];

    int x = tsum;
    #pragma unroll
    for (int off = 1; off < 32; off <<= 1) {
        int y = __shfl_up_sync(0xffffffffu, x, off);
        if (lane >= off) x += y;
    }
    if (lane == 31) warp_tot[w] = x;
    __syncthreads();

    if (w == 0) {
        int s = warp_tot[lane];
        #pragma unroll
        for (int off = 1; off < 32; off <<= 1) {
            int y = __shfl_up_sync(0xffffffffu, s, off);
            if (lane >= off) s += y;
        }
        warp_tot[lane] = s;
    }
    __syncthreads();

    int warp_excl = (w == 0) ? 0 : warp_tot[w - 1];
    int acc = warp_excl + x - tsum;   // exclusive prefix for this thread

    for (int i = lo; i < hi; i++) {
        int v = g_counts[i];
        g_rowptr[i] = acc;
        g_cursor[i] = acc;
        acc += v;
    }
    if (t == 0) g_rowptr[N] = E;
}

// Scatter cols into row-grouped order: 4 edges/thread for atomic MLP
__global__ void build_scol_kernel(const int* __restrict__ ei, int E) {
    int i = blockIdx.x * blockDim.x + threadIdx.x;
    int e4 = i * 4;
    if (e4 + 4 <= E) {
        int4 r = __ldg(reinterpret_cast<const int4*>(ei + e4));
        int4 c = __ldg(reinterpret_cast<const int4*>(ei + E + e4));
        int p0 = atomicAdd(&g_cursor[r.x], 1);
        int p1 = atomicAdd(&g_cursor[r.y], 1);
        int p2 = atomicAdd(&g_cursor[r.z], 1);
        int p3 = atomicAdd(&g_cursor[r.w], 1);
        g_scol[p0] = c.x;
        g_scol[p1] = c.y;
        g_scol[p2] = c.z;
        g_scol[p3] = c.w;
    } else {
        for (int e = e4; e < E; e++) {
            int row = __ldg(&ei[e]);
            int col = __ldg(&ei[E + e]);
            int pos = atomicAdd(&g_cursor[row], 1);
            g_scol[pos] = col;
        }
    }
}

// ---------------- fused pull + bias + log_softmax (R4 body) ----------------

__global__ void pull_kernel(const float* __restrict__ Wt,
                            const float* __restrict__ b,
                            float* __restrict__ out,
                            int N) {
    int warp = (blockIdx.x * blockDim.x + threadIdx.x) >> 5;
    int lane = threadIdx.x & 31;
    if (warp >= N) return;

    int start = __ldg(&g_rowptr[warp]);
    int end   = __ldg(&g_rowptr[warp + 1]);

    const float2* bb = reinterpret_cast<const float2*>(b);
    float2 acc = __ldg(&bb[lane]);     // cols [2*lane, 2*lane+1]

    int j = start;
    for (; j + 4 <= end; j += 4) {
        int c0 = __ldg(&g_scol[j]);
        int c1 = __ldg(&g_scol[j + 1]);
        int c2 = __ldg(&g_scol[j + 2]);
        int c3 = __ldg(&g_scol[j + 3]);
        float2 v0 = __ldg(reinterpret_cast<const float2*>(Wt + (size_t)c0 * C) + lane);
        float2 v1 = __ldg(reinterpret_cast<const float2*>(Wt + (size_t)c1 * C) + lane);
        float2 v2 = __ldg(reinterpret_cast<const float2*>(Wt + (size_t)c2 * C) + lane);
        float2 v3 = __ldg(reinterpret_cast<const float2*>(Wt + (size_t)c3 * C) + lane);
        acc.x += (v0.x + v1.x) + (v2.x + v3.x);
        acc.y += (v0.y + v1.y) + (v2.y + v3.y);
    }
    for (; j < end; j++) {
        int c = __ldg(&g_scol[j]);
        float2 v = __ldg(reinterpret_cast<const float2*>(Wt + (size_t)c * C) + lane);
        acc.x += v.x;
        acc.y += v.y;
    }

    // log_softmax over 64 values held as 32 x float2
    float mx = fmaxf(acc.x, acc.y);
    #pragma unroll
    for (int off = 16; off > 0; off >>= 1)
        mx = fmaxf(mx, __shfl_xor_sync(0xffffffffu, mx, off));

    float s = __expf(acc.x - mx) + __expf(acc.y - mx);
    #pragma unroll
    for (int off = 16; off > 0; off >>= 1)
        s += __shfl_xor_sync(0xffffffffu, s, off);

    float lse = mx + logf(s);
    float2 o = make_float2(acc.x - lse, acc.y - lse);
    reinterpret_cast<float2*>(out + (size_t)warp * C)[lane] = o;
}

// ---------------- fallback (push w/ atomics) for unexpected sizes ----------------

__global__ void init_kernel(float* __restrict__ out, const float* __restrict__ b, int total) {
    int i = blockIdx.x * blockDim.x + threadIdx.x;
    if (i < total) out[i] = __ldg(&b[i & (C - 1)]);
}

__global__ void scatter_kernel(const int* __restrict__ ei, const float* __restrict__ Wt,
                               float* __restrict__ out, int E) {
    int gtid = blockIdx.x * blockDim.x + threadIdx.x;
    int e = gtid >> 4;
    int lane = threadIdx.x & 15;
    if (e >= E) return;
    int row = __ldg(&ei[e]);
    int col = __ldg(&ei[E + e]);
    const float4* src = reinterpret_cast<const float4*>(Wt + (long long)col * C);
    float4 v = __ldg(&src[lane]);
    float* dst = out + (long long)row * C + lane * 4;
    asm volatile("red.global.add.v4.f32 [%0], {%1, %2, %3, %4};"
                 :: "l"(dst), "f"(v.x), "f"(v.y), "f"(v.z), "f"(v.w) : "memory");
}

__global__ void softmax_kernel(float* __restrict__ out, int N) {
    int warp = (blockIdx.x * blockDim.x + threadIdx.x) >> 5;
    int lane = threadIdx.x & 31;
    if (warp >= N) return;
    float* rowp = out + (long long)warp * C;
    float v0 = rowp[lane];
    float v1 = rowp[lane + 32];
    float m = fmaxf(v0, v1);
    #pragma unroll
    for (int off = 16; off > 0; off >>= 1)
        m = fmaxf(m, __shfl_xor_sync(0xffffffffu, m, off));
    float s = __expf(v0 - m) + __expf(v1 - m);
    #pragma unroll
    for (int off = 16; off > 0; off >>= 1)
        s += __shfl_xor_sync(0xffffffffu, s, off);
    float lse = m + logf(s);
    rowp[lane]      = v0 - lse;
    rowp[lane + 32] = v1 - lse;
}

// ---------------- launch ----------------

extern "C" void kernel_launch(void* const* d_in, const int* in_sizes, int n_in,
                              void* d_out, int out_size) {
    const int*   ei = (const int*)d_in[0];   // [2, E] int32
    const float* Wt = (const float*)d_in[1]; // [N, C]
    const float* b  = (const float*)d_in[2]; // [C]
    float* out = (float*)d_out;              // [N, C]

    int E = in_sizes[0] / 2;
    int N = in_sizes[1] / C;

    if (N <= MAX_N && E <= MAX_E) {
        zero_counts_kernel<<<(N + 256) / 256, 256>>>(N);
        hist_kernel<<<((E + 3) / 4 + 255) / 256, 256>>>(ei, E);
        fused_scan_kernel<<<1, SCAN_THREADS>>>(N, E);
        build_scol_kernel<<<((E + 3) / 4 + 255) / 256, 256>>>(ei, E);

        int threads = 256; // 8 warps per block
        int blocks = (N + 7) / 8;
        pull_kernel<<<blocks, threads>>>(Wt, b, out, N);
    } else {
        int total = N * C;
        init_kernel<<<(total + 255) / 256, 256>>>(out, b, total);
        long long work = (long long)E * 16;
        scatter_kernel<<<(int)((work + 255) / 256), 256>>>(ei, Wt, out, E);
        softmax_kernel<<<(N + 7) / 8, 256>>>(out, N);
    }
}

// round 9
// speedup vs baseline: 2.2450x; 2.2450x over previous
#include <cuda_runtime.h>
#include <cuda_bf16.h>

// logits[i] = sum_{(i,j) in E} Wt[j] + b ; out = log_softmax(logits, axis=1)
// N=100000, E=3200000, C=64. edge_index int32 [2,E].
//
// R9: multi-block scan restored (R6/R8's single-block fused scan serialized
// ~400k ld/st on ONE SM, +160us). scan2 parallelized. build_scol at 8
// edges/thread for atomic-return MLP. Pull = R4 body (near L2 roofline).

#define C 64
#define MAX_N 100000
#define MAX_E 3200000
#define SCAN_BLOCK 1024
#define MAX_SCAN_BLOCKS 128   // ceil(MAX_N / SCAN_BLOCK) = 98

__device__ int g_counts[MAX_N + 1];
__device__ int g_rowptr[MAX_N + 1];
__device__ int g_cursor[MAX_N + 1];
__device__ int g_blocksums[MAX_SCAN_BLOCKS];
__device__ int g_scol[MAX_E];

// ---------------- CSR build ----------------

__global__ void zero_counts_kernel(int N) {
    int i = blockIdx.x * blockDim.x + threadIdx.x;
    if (i <= N) g_counts[i] = 0;
}

__global__ void hist_kernel(const int* __restrict__ ei, int E) {
    int i = blockIdx.x * blockDim.x + threadIdx.x;
    int e4 = i * 4;
    if (e4 + 4 <= E) {
        int4 r = __ldg(reinterpret_cast<const int4*>(ei + e4));
        atomicAdd(&g_counts[r.x], 1);
        atomicAdd(&g_counts[r.y], 1);
        atomicAdd(&g_counts[r.z], 1);
        atomicAdd(&g_counts[r.w], 1);
    } else {
        for (int e = e4; e < E; e++) atomicAdd(&g_counts[ei[e]], 1);
    }
}

// Per-block exclusive scan of g_counts -> g_rowptr (block-local), totals -> g_blocksums
__global__ void scan1_kernel(int N) {
    __shared__ int wsum[32];
    int t = threadIdx.x;
    int i = blockIdx.x * SCAN_BLOCK + t;
    int lane = t & 31, w = t >> 5;

    int val = (i < N) ? g_counts[i] : 0;

    int x = val;
    #pragma unroll
    for (int off = 1; off < 32; off <<= 1) {
        int y = __shfl_up_sync(0xffffffffu, x, off);
        if (lane >= off) x += y;
    }
    if (lane == 31) wsum[w] = x;
    __syncthreads();

    if (w == 0) {
        int s = wsum[lane];
        #pragma unroll
        for (int off = 1; off < 32; off <<= 1) {
            int y = __shfl_up_sync(0xffffffffu, s, off);
            if (lane >= off) s += y;
        }
        wsum[lane] = s;
    }
    __syncthreads();

    int warp_excl = (w == 0) ? 0 : wsum[w - 1];
    int excl = warp_excl + x - val;
    if (i < N) g_rowptr[i] = excl;
    if (t == SCAN_BLOCK - 1) g_blocksums[blockIdx.x] = warp_excl + x;
}

// Exclusive scan of <=128 block sums: one warp, 4 elems/lane
__global__ void scan2_kernel(int nblocks) {
    int lane = threadIdx.x;   // 32 threads
    int base = lane * 4;

    int v0 = (base + 0 < nblocks) ? g_blocksums[base + 0] : 0;
    int v1 = (base + 1 < nblocks) ? g_blocksums[base + 1] : 0;
    int v2 = (base + 2 < nblocks) ? g_blocksums[base + 2] : 0;
    int v3 = (base + 3 < nblocks) ? g_blocksums[base + 3] : 0;

    int tsum = v0 + v1 + v2 + v3;
    int x = tsum;
    #pragma unroll
    for (int off = 1; off < 32; off <<= 1) {
        int y = __shfl_up_sync(0xffffffffu, x, off);
        if (lane >= off) x += y;
    }
    int excl = x - tsum;

    if (base + 0 < nblocks) g_blocksums[base + 0] = excl;
    if (base + 1 < nblocks) g_blocksums[base + 1] = excl + v0;
    if (base + 2 < nblocks) g_blocksums[base + 2] = excl + v0 + v1;
    if (base + 3 < nblocks) g_blocksums[base + 3] = excl + v0 + v1 + v2;
}

// Add block offsets; init cursors; rowptr[N] = E
__global__ void scan3_kernel(int N, int E) {
    int i = blockIdx.x * blockDim.x + threadIdx.x;
    if (i < N) {
        int v = g_rowptr[i] + g_blocksums[i / SCAN_BLOCK];
        g_rowptr[i] = v;
        g_cursor[i] = v;
    }
    if (i == 0) g_rowptr[N] = E;
}

// Scatter cols into row-grouped order: 8 edges/thread for atomic-return MLP
__global__ void build_scol_kernel(const int* __restrict__ ei, int E) {
    int i = blockIdx.x * blockDim.x + threadIdx.x;
    int e8 = i * 8;
    if (e8 + 8 <= E) {
        int4 ra = __ldg(reinterpret_cast<const int4*>(ei + e8));
        int4 rb = __ldg(reinterpret_cast<const int4*>(ei + e8 + 4));
        int4 ca = __ldg(reinterpret_cast<const int4*>(ei + E + e8));
        int4 cb = __ldg(reinterpret_cast<const int4*>(ei + E + e8 + 4));
        int p0 = atomicAdd(&g_cursor[ra.x], 1);
        int p1 = atomicAdd(&g_cursor[ra.y], 1);
        int p2 = atomicAdd(&g_cursor[ra.z], 1);
        int p3 = atomicAdd(&g_cursor[ra.w], 1);
        int p4 = atomicAdd(&g_cursor[rb.x], 1);
        int p5 = atomicAdd(&g_cursor[rb.y], 1);
        int p6 = atomicAdd(&g_cursor[rb.z], 1);
        int p7 = atomicAdd(&g_cursor[rb.w], 1);
        g_scol[p0] = ca.x;
        g_scol[p1] = ca.y;
        g_scol[p2] = ca.z;
        g_scol[p3] = ca.w;
        g_scol[p4] = cb.x;
        g_scol[p5] = cb.y;
        g_scol[p6] = cb.z;
        g_scol[p7] = cb.w;
    } else {
        for (int e = e8; e < E; e++) {
            int row = __ldg(&ei[e]);
            int col = __ldg(&ei[E + e]);
            int pos = atomicAdd(&g_cursor[row], 1);
            g_scol[pos] = col;
        }
    }
}

// ---------------- fused pull + bias + log_softmax (R4 body) ----------------

__global__ void pull_kernel(const float* __restrict__ Wt,
                            const float* __restrict__ b,
                            float* __restrict__ out,
                            int N) {
    int warp = (blockIdx.x * blockDim.x + threadIdx.x) >> 5;
    int lane = threadIdx.x & 31;
    if (warp >= N) return;

    int start = __ldg(&g_rowptr[warp]);
    int end   = __ldg(&g_rowptr[warp + 1]);

    const float2* bb = reinterpret_cast<const float2*>(b);
    float2 acc = __ldg(&bb[lane]);     // cols [2*lane, 2*lane+1]

    int j = start;
    for (; j + 4 <= end; j += 4) {
        int c0 = __ldg(&g_scol[j]);
        int c1 = __ldg(&g_scol[j + 1]);
        int c2 = __ldg(&g_scol[j + 2]);
        int c3 = __ldg(&g_scol[j + 3]);
        float2 v0 = __ldg(reinterpret_cast<const float2*>(Wt + (size_t)c0 * C) + lane);
        float2 v1 = __ldg(reinterpret_cast<const float2*>(Wt + (size_t)c1 * C) + lane);
        float2 v2 = __ldg(reinterpret_cast<const float2*>(Wt + (size_t)c2 * C) + lane);
        float2 v3 = __ldg(reinterpret_cast<const float2*>(Wt + (size_t)c3 * C) + lane);
        acc.x += (v0.x + v1.x) + (v2.x + v3.x);
        acc.y += (v0.y + v1.y) + (v2.y + v3.y);
    }
    for (; j < end; j++) {
        int c = __ldg(&g_scol[j]);
        float2 v = __ldg(reinterpret_cast<const float2*>(Wt + (size_t)c * C) + lane);
        acc.x += v.x;
        acc.y += v.y;
    }

    float mx = fmaxf(acc.x, acc.y);
    #pragma unroll
    for (int off = 16; off > 0; off >>= 1)
        mx = fmaxf(mx, __shfl_xor_sync(0xffffffffu, mx, off));

    float s = __expf(acc.x - mx) + __expf(acc.y - mx);
    #pragma unroll
    for (int off = 16; off > 0; off >>= 1)
        s += __shfl_xor_sync(0xffffffffu, s, off);

    float lse = mx + logf(s);
    float2 o = make_float2(acc.x - lse, acc.y - lse);
    reinterpret_cast<float2*>(out + (size_t)warp * C)[lane] = o;
}

// ---------------- fallback (push w/ atomics) for unexpected sizes ----------------

__global__ void init_kernel(float* __restrict__ out, const float* __restrict__ b, int total) {
    int i = blockIdx.x * blockDim.x + threadIdx.x;
    if (i < total) out[i] = __ldg(&b[i & (C - 1)]);
}

__global__ void scatter_kernel(const int* __restrict__ ei, const float* __restrict__ Wt,
                               float* __restrict__ out, int E) {
    int gtid = blockIdx.x * blockDim.x + threadIdx.x;
    int e = gtid >> 4;
    int lane = threadIdx.x & 15;
    if (e >= E) return;
    int row = __ldg(&ei[e]);
    int col = __ldg(&ei[E + e]);
    const float4* src = reinterpret_cast<const float4*>(Wt + (long long)col * C);
    float4 v = __ldg(&src[lane]);
    float* dst = out + (long long)row * C + lane * 4;
    asm volatile("red.global.add.v4.f32 [%0], {%1, %2, %3, %4};"
                 :: "l"(dst), "f"(v.x), "f"(v.y), "f"(v.z), "f"(v.w) : "memory");
}

__global__ void softmax_kernel(float* __restrict__ out, int N) {
    int warp = (blockIdx.x * blockDim.x + threadIdx.x) >> 5;
    int lane = threadIdx.x & 31;
    if (warp >= N) return;
    float* rowp = out + (long long)warp * C;
    float v0 = rowp[lane];
    float v1 = rowp[lane + 32];
    float m = fmaxf(v0, v1);
    #pragma unroll
    for (int off = 16; off > 0; off >>= 1)
        m = fmaxf(m, __shfl_xor_sync(0xffffffffu, m, off));
    float s = __expf(v0 - m) + __expf(v1 - m);
    #pragma unroll
    for (int off = 16; off > 0; off >>= 1)
        s += __shfl_xor_sync(0xffffffffu, s, off);
    float lse = m + logf(s);
    rowp[lane]      = v0 - lse;
    rowp[lane + 32] = v1 - lse;
}

// ---------------- launch ----------------

extern "C" void kernel_launch(void* const* d_in, const int* in_sizes, int n_in,
                              void* d_out, int out_size) {
    const int*   ei = (const int*)d_in[0];   // [2, E] int32
    const float* Wt = (const float*)d_in[1]; // [N, C]
    const float* b  = (const float*)d_in[2]; // [C]
    float* out = (float*)d_out;              // [N, C]

    int E = in_sizes[0] / 2;
    int N = in_sizes[1] / C;

    if (N <= MAX_N && E <= MAX_E) {
        int nblocks_scan = (N + SCAN_BLOCK - 1) / SCAN_BLOCK;

        zero_counts_kernel<<<(N + 256) / 256, 256>>>(N);
        hist_kernel<<<((E + 3) / 4 + 255) / 256, 256>>>(ei, E);
        scan1_kernel<<<nblocks_scan, SCAN_BLOCK>>>(N);
        scan2_kernel<<<1, 32>>>(nblocks_scan);
        scan3_kernel<<<(N + SCAN_BLOCK - 1) / SCAN_BLOCK, SCAN_BLOCK>>>(N, E);
        build_scol_kernel<<<((E + 7) / 8 + 255) / 256, 256>>>(ei, E);

        int threads = 256; // 8 warps per block
        int blocks = (N + 7) / 8;
        pull_kernel<<<blocks, threads>>>(Wt, b, out, N);
    } else {
        int total = N * C;
        init_kernel<<<(total + 255) / 256, 256>>>(out, b, total);
        long long work = (long long)E * 16;
        scatter_kernel<<<(int)((work + 255) / 256), 256>>>(ei, Wt, out, E);
        softmax_kernel<<<(N + 7) / 8, 256>>>(out, N);
    }
}

// round 10
// speedup vs baseline: 2.3223x; 1.0344x over previous
#include <cuda_runtime.h>
#include <cuda_bf16.h>

// logits[i] = sum_{(i,j) in E} Wt[j] + b ; out = log_softmax(logits, axis=1)
// N=100000, E=3200000, C=64. edge_index int32 [2,E].
//
// R10: single atomic per edge. hist computes per-edge rank via atomicAdd
// return and packs (row<<15)|rank. build_scol becomes atomic-free:
// pos = rowptr[row] + rank. Halves the LTS small-op count that bound R9's
// build_scol (46us). Pull = proven R4 body.

#define C 64
#define MAX_N 100000       // must stay < 131072 for 17-bit row packing
#define MAX_E 3200000
#define SCAN_BLOCK 1024
#define MAX_SCAN_BLOCKS 128

__device__ int g_counts[MAX_N + 1];
__device__ int g_rowptr[MAX_N + 1];
__device__ int g_blocksums[MAX_SCAN_BLOCKS];
__device__ unsigned int g_pack[MAX_E];   // (row << 15) | rank
__device__ int g_scol[MAX_E];

// ---------------- CSR build ----------------

__global__ void zero_counts_kernel(int N) {
    int i = blockIdx.x * blockDim.x + threadIdx.x;
    if (i <= N) g_counts[i] = 0;
}

// Histogram + per-edge rank capture (single atomic per edge)
__global__ void hist_rank_kernel(const int* __restrict__ ei, int E) {
    int i = blockIdx.x * blockDim.x + threadIdx.x;
    int e4 = i * 4;
    if (e4 + 4 <= E) {
        int4 r = __ldg(reinterpret_cast<const int4*>(ei + e4));
        int k0 = atomicAdd(&g_counts[r.x], 1);
        int k1 = atomicAdd(&g_counts[r.y], 1);
        int k2 = atomicAdd(&g_counts[r.z], 1);
        int k3 = atomicAdd(&g_counts[r.w], 1);
        uint4 p;
        p.x = ((unsigned)r.x << 15) | (unsigned)k0;
        p.y = ((unsigned)r.y << 15) | (unsigned)k1;
        p.z = ((unsigned)r.z << 15) | (unsigned)k2;
        p.w = ((unsigned)r.w << 15) | (unsigned)k3;
        *reinterpret_cast<uint4*>(g_pack + e4) = p;
    } else {
        for (int e = e4; e < E; e++) {
            int row = __ldg(&ei[e]);
            int k = atomicAdd(&g_counts[row], 1);
            g_pack[e] = ((unsigned)row << 15) | (unsigned)k;
        }
    }
}

// Per-block exclusive scan of g_counts -> g_rowptr (block-local), totals -> g_blocksums
__global__ void scan1_kernel(int N) {
    __shared__ int wsum[32];
    int t = threadIdx.x;
    int i = blockIdx.x * SCAN_BLOCK + t;
    int lane = t & 31, w = t >> 5;

    int val = (i < N) ? g_counts[i] : 0;

    int x = val;
    #pragma unroll
    for (int off = 1; off < 32; off <<= 1) {
        int y = __shfl_up_sync(0xffffffffu, x, off);
        if (lane >= off) x += y;
    }
    if (lane == 31) wsum[w] = x;
    __syncthreads();

    if (w == 0) {
        int s = wsum[lane];
        #pragma unroll
        for (int off = 1; off < 32; off <<= 1) {
            int y = __shfl_up_sync(0xffffffffu, s, off);
            if (lane >= off) s += y;
        }
        wsum[lane] = s;
    }
    __syncthreads();

    int warp_excl = (w == 0) ? 0 : wsum[w - 1];
    int excl = warp_excl + x - val;
    if (i < N) g_rowptr[i] = excl;
    if (t == SCAN_BLOCK - 1) g_blocksums[blockIdx.x] = warp_excl + x;
}

// Exclusive scan of <=128 block sums: one warp, 4 elems/lane
__global__ void scan2_kernel(int nblocks) {
    int lane = threadIdx.x;
    int base = lane * 4;

    int v0 = (base + 0 < nblocks) ? g_blocksums[base + 0] : 0;
    int v1 = (base + 1 < nblocks) ? g_blocksums[base + 1] : 0;
    int v2 = (base + 2 < nblocks) ? g_blocksums[base + 2] : 0;
    int v3 = (base + 3 < nblocks) ? g_blocksums[base + 3] : 0;

    int tsum = v0 + v1 + v2 + v3;
    int x = tsum;
    #pragma unroll
    for (int off = 1; off < 32; off <<= 1) {
        int y = __shfl_up_sync(0xffffffffu, x, off);
        if (lane >= off) x += y;
    }
    int excl = x - tsum;

    if (base + 0 < nblocks) g_blocksums[base + 0] = excl;
    if (base + 1 < nblocks) g_blocksums[base + 1] = excl + v0;
    if (base + 2 < nblocks) g_blocksums[base + 2] = excl + v0 + v1;
    if (base + 3 < nblocks) g_blocksums[base + 3] = excl + v0 + v1 + v2;
}

// Add block offsets; rowptr[N] = E
__global__ void scan3_kernel(int N, int E) {
    int i = blockIdx.x * blockDim.x + threadIdx.x;
    if (i < N) {
        g_rowptr[i] += g_blocksums[i / SCAN_BLOCK];
    }
    if (i == 0) g_rowptr[N] = E;
}

// Atomic-free scatter: pos = rowptr[row] + rank
__global__ void build_scol_kernel(const int* __restrict__ ei, int E) {
    int i = blockIdx.x * blockDim.x + threadIdx.x;
    int e4 = i * 4;
    if (e4 + 4 <= E) {
        uint4 p = __ldg(reinterpret_cast<const uint4*>(g_pack + e4));
        int4  c = __ldg(reinterpret_cast<const int4*>(ei + E + e4));
        int p0 = __ldg(&g_rowptr[p.x >> 15]) + (int)(p.x & 0x7FFFu);
        int p1 = __ldg(&g_rowptr[p.y >> 15]) + (int)(p.y & 0x7FFFu);
        int p2 = __ldg(&g_rowptr[p.z >> 15]) + (int)(p.z & 0x7FFFu);
        int p3 = __ldg(&g_rowptr[p.w >> 15]) + (int)(p.w & 0x7FFFu);
        g_scol[p0] = c.x;
        g_scol[p1] = c.y;
        g_scol[p2] = c.z;
        g_scol[p3] = c.w;
    } else {
        for (int e = e4; e < E; e++) {
            unsigned p = g_pack[e];
            int col = __ldg(&ei[E + e]);
            int pos = g_rowptr[p >> 15] + (int)(p & 0x7FFFu);
            g_scol[pos] = col;
        }
    }
}

// ---------------- fused pull + bias + log_softmax (R4 body) ----------------

__global__ void pull_kernel(const float* __restrict__ Wt,
                            const float* __restrict__ b,
                            float* __restrict__ out,
                            int N) {
    int warp = (blockIdx.x * blockDim.x + threadIdx.x) >> 5;
    int lane = threadIdx.x & 31;
    if (warp >= N) return;

    int start = __ldg(&g_rowptr[warp]);
    int end   = __ldg(&g_rowptr[warp + 1]);

    const float2* bb = reinterpret_cast<const float2*>(b);
    float2 acc = __ldg(&bb[lane]);     // cols [2*lane, 2*lane+1]

    int j = start;
    for (; j + 4 <= end; j += 4) {
        int c0 = __ldg(&g_scol[j]);
        int c1 = __ldg(&g_scol[j + 1]);
        int c2 = __ldg(&g_scol[j + 2]);
        int c3 = __ldg(&g_scol[j + 3]);
        float2 v0 = __ldg(reinterpret_cast<const float2*>(Wt + (size_t)c0 * C) + lane);
        float2 v1 = __ldg(reinterpret_cast<const float2*>(Wt + (size_t)c1 * C) + lane);
        float2 v2 = __ldg(reinterpret_cast<const float2*>(Wt + (size_t)c2 * C) + lane);
        float2 v3 = __ldg(reinterpret_cast<const float2*>(Wt + (size_t)c3 * C) + lane);
        acc.x += (v0.x + v1.x) + (v2.x + v3.x);
        acc.y += (v0.y + v1.y) + (v2.y + v3.y);
    }
    for (; j < end; j++) {
        int c = __ldg(&g_scol[j]);
        float2 v = __ldg(reinterpret_cast<const float2*>(Wt + (size_t)c * C) + lane);
        acc.x += v.x;
        acc.y += v.y;
    }

    float mx = fmaxf(acc.x, acc.y);
    #pragma unroll
    for (int off = 16; off > 0; off >>= 1)
        mx = fmaxf(mx, __shfl_xor_sync(0xffffffffu, mx, off));

    float s = __expf(acc.x - mx) + __expf(acc.y - mx);
    #pragma unroll
    for (int off = 16; off > 0; off >>= 1)
        s += __shfl_xor_sync(0xffffffffu, s, off);

    float lse = mx + logf(s);
    float2 o = make_float2(acc.x - lse, acc.y - lse);
    reinterpret_cast<float2*>(out + (size_t)warp * C)[lane] = o;
}

// ---------------- fallback (push w/ atomics) for unexpected sizes ----------------

__global__ void init_kernel(float* __restrict__ out, const float* __restrict__ b, int total) {
    int i = blockIdx.x * blockDim.x + threadIdx.x;
    if (i < total) out[i] = __ldg(&b[i & (C - 1)]);
}

__global__ void scatter_kernel(const int* __restrict__ ei, const float* __restrict__ Wt,
                               float* __restrict__ out, int E) {
    int gtid = blockIdx.x * blockDim.x + threadIdx.x;
    int e = gtid >> 4;
    int lane = threadIdx.x & 15;
    if (e >= E) return;
    int row = __ldg(&ei[e]);
    int col = __ldg(&ei[E + e]);
    const float4* src = reinterpret_cast<const float4*>(Wt + (long long)col * C);
    float4 v = __ldg(&src[lane]);
    float* dst = out + (long long)row * C + lane * 4;
    asm volatile("red.global.add.v4.f32 [%0], {%1, %2, %3, %4};"
                 :: "l"(dst), "f"(v.x), "f"(v.y), "f"(v.z), "f"(v.w) : "memory");
}

__global__ void softmax_kernel(float* __restrict__ out, int N) {
    int warp = (blockIdx.x * blockDim.x + threadIdx.x) >> 5;
    int lane = threadIdx.x & 31;
    if (warp >= N) return;
    float* rowp = out + (long long)warp * C;
    float v0 = rowp[lane];
    float v1 = rowp[lane + 32];
    float m = fmaxf(v0, v1);
    #pragma unroll
    for (int off = 16; off > 0; off >>= 1)
        m = fmaxf(m, __shfl_xor_sync(0xffffffffu, m, off));
    float s = __expf(v0 - m) + __expf(v1 - m);
    #pragma unroll
    for (int off = 16; off > 0; off >>= 1)
        s += __shfl_xor_sync(0xffffffffu, s, off);
    float lse = m + logf(s);
    rowp[lane]      = v0 - lse;
    rowp[lane + 32] = v1 - lse;
}

// ---------------- launch ----------------

extern "C" void kernel_launch(void* const* d_in, const int* in_sizes, int n_in,
                              void* d_out, int out_size) {
    const int*   ei = (const int*)d_in[0];   // [2, E] int32
    const float* Wt = (const float*)d_in[1]; // [N, C]
    const float* b  = (const float*)d_in[2]; // [C]
    float* out = (float*)d_out;              // [N, C]

    int E = in_sizes[0] / 2;
    int N = in_sizes[1] / C;

    if (N <= MAX_N && E <= MAX_E) {
        int nblocks_scan = (N + SCAN_BLOCK - 1) / SCAN_BLOCK;

        zero_counts_kernel<<<(N + 256) / 256, 256>>>(N);
        hist_rank_kernel<<<((E + 3) / 4 + 255) / 256, 256>>>(ei, E);
        scan1_kernel<<<nblocks_scan, SCAN_BLOCK>>>(N);
        scan2_kernel<<<1, 32>>>(nblocks_scan);
        scan3_kernel<<<(N + SCAN_BLOCK - 1) / SCAN_BLOCK, SCAN_BLOCK>>>(N, E);
        build_scol_kernel<<<((E + 3) / 4 + 255) / 256, 256>>>(ei, E);

        int threads = 256; // 8 warps per block
        int blocks = (N + 7) / 8;
        pull_kernel<<<blocks, threads>>>(Wt, b, out, N);
    } else {
        int total = N * C;
        init_kernel<<<(total + 255) / 256, 256>>>(out, b, total);
        long long work = (long long)E * 16;
        scatter_kernel<<<(int)((work + 255) / 256), 256>>>(ei, Wt, out, E);
        softmax_kernel<<<(N + 7) / 8, 256>>>(out, N);
    }
}